// round 10
// baseline (speedup 1.0000x reference)
#include <cuda_runtime.h>
#include <math.h>

// Problem dims
#define HID 64
#define CIN 4
#define EPSV 1e-12f

// Packed weight scratch (filled by prep kernel every launch; deterministic).
// wp0: [net][o][tap*4 + i]          (mask-A taps: kidx 0..3)
// wp1: [net][o][tap][i]             (mask-B taps: kidx 0..4)
// wp2: [net][o][tap][i]
__device__ __align__(16) float g_wp0[2 * 64 * 16];
__device__ __align__(16) float g_wp1[2 * 64 * 5 * 64];
__device__ __align__(16) float g_wp2[2 * 64 * 5 * 64];

__global__ void pack_weights_kernel(
    const float* __restrict__ mw0, const float* __restrict__ mw1, const float* __restrict__ mw2,
    const float* __restrict__ lw0, const float* __restrict__ lw1, const float* __restrict__ lw2)
{
    int idx = blockIdx.x * blockDim.x + threadIdx.x;
    if (idx < 40960) {
        // g_wp1: linear = net*20480 + o*320 + tap*64 + i
        int i   = idx & 63;
        int tap = (idx >> 6) % 5;
        int o   = (idx / 320) & 63;
        int net = idx / 20480;
        const float* src = net ? lw1 : mw1;
        g_wp1[idx] = src[o * 576 + i * 9 + tap];
    } else if (idx < 81920) {
        int k   = idx - 40960;
        int i   = k & 63;
        int tap = (k >> 6) % 5;
        int o   = (k / 320) & 63;
        int net = k / 20480;
        const float* src = net ? lw2 : mw2;
        g_wp2[k] = src[o * 576 + i * 9 + tap];
    } else if (idx < 83968) {
        int k   = idx - 81920;
        int i   = k & 3;
        int tap = (k >> 2) & 3;
        int o   = (k >> 4) & 63;
        int net = k >> 10;
        const float* src = net ? lw0 : mw0;
        g_wp0[k] = src[o * 36 + i * 9 + tap];
    }
}

__device__ __forceinline__ float eluf(float v) { return v > 0.f ? v : expm1f(v); }

// One CTA per batch element. Sequential raster decode of 64 pixels.
// Phases per pixel: A: h0(p) (mask-A conv on y) -> B: h1(p) -> C: h2(p)
// -> D: 1x1 out (mu, lv_raw) -> E: y(p) = (x - mu)/(exp(0.5*lv)+eps).
__global__ __launch_bounds__(512, 1)
void made_ar_kernel(const float* __restrict__ x,
                    const float* __restrict__ mb0, const float* __restrict__ mb1,
                    const float* __restrict__ mb2, const float* __restrict__ mwo,
                    const float* __restrict__ mbo,
                    const float* __restrict__ lb0, const float* __restrict__ lb1,
                    const float* __restrict__ lb2, const float* __restrict__ lwo,
                    const float* __restrict__ lbo,
                    float* __restrict__ out)
{
    __shared__ __align__(16) float s_h0[2][2][8][64];  // [net][row ring][col][ch]
    __shared__ __align__(16) float s_h1[2][2][8][64];
    __shared__ __align__(16) float s_h2[2][64];        // post-ELU, transient per pixel
    __shared__ float s_y[4 * 64];                      // [C][H*W]
    __shared__ float s_x[4 * 64];
    __shared__ float s_res[2][4];                      // mu raw / lv raw per channel
    __shared__ float s_ls[4];

    const int tid = threadIdx.x;
    const int b   = blockIdx.x;

    if (tid < 256) s_x[tid] = x[b * 256 + tid];

    // ---- Phase-A constants (threads 0..127): net = tid>>6, o = tid&63 ----
    const int netA = tid >> 6;
    const int oA   = tid & 63;
    float4 w0r0, w0r1, w0r2, w0r3;
    float  biasA = 0.f;
    if (tid < 128) {
        const float4* wp = reinterpret_cast<const float4*>(&g_wp0[(netA * 64 + oA) * 16]);
        w0r0 = wp[0]; w0r1 = wp[1]; w0r2 = wp[2]; w0r3 = wp[3];
        biasA = (netA ? lb0 : mb0)[oA];
    }

    // ---- Phase-B/C constants: quarter-split of 320-MAC dot products ----
    const int q   = tid & 3;           // quarter of input channels
    const int o   = (tid >> 2) & 63;   // output channel
    const int net = tid >> 8;          // 0 = mu, 1 = lv (warp-uniform)
    const float bias1 = (net ? lb1 : mb1)[o];
    const float bias2 = (net ? lb2 : mb2)[o];
    const float* w1base = &g_wp1[((net * 64 + o) * 5) * 64 + q * 16];
    const float* w2base = &g_wp2[((net * 64 + o) * 5) * 64 + q * 16];

    // ---- Phase-D constants: warps 0..7 -> (net, out channel) ----
    const int warp = tid >> 5, lane = tid & 31;
    const int netD = warp >> 2, cD = warp & 3;
    float woA = 0.f, woB = 0.f, boD = 0.f;
    if (warp < 8) {
        const float* wo = netD ? lwo : mwo;
        woA = wo[cD * 64 + lane];
        woB = wo[cD * 64 + 32 + lane];
        boD = (netD ? lbo : mbo)[cD];
    }

    float ls_acc = 0.f;
    __syncthreads();

    const int DY[5] = {-1, -1, -1, 0, 0};
    const int DX[5] = {-1,  0,  1, -1, 0};

    for (int p = 0; p < 64; ++p) {
        const int r = p >> 3, c = p & 7;

        // ---------------- Phase A: h0(p) = elu(maskA-conv(y) + b0) ----------------
        if (tid < 128) {
            float acc = biasA;
            if (r > 0) {
                const int base = (r - 1) * 8 + c;
                if (c > 0) {
                    const float* yy = &s_y[base - 1];
                    acc += w0r0.x * yy[0] + w0r0.y * yy[64] + w0r0.z * yy[128] + w0r0.w * yy[192];
                }
                {
                    const float* yy = &s_y[base];
                    acc += w0r1.x * yy[0] + w0r1.y * yy[64] + w0r1.z * yy[128] + w0r1.w * yy[192];
                }
                if (c < 7) {
                    const float* yy = &s_y[base + 1];
                    acc += w0r2.x * yy[0] + w0r2.y * yy[64] + w0r2.z * yy[128] + w0r2.w * yy[192];
                }
            }
            if (c > 0) {
                const float* yy = &s_y[r * 8 + c - 1];
                acc += w0r3.x * yy[0] + w0r3.y * yy[64] + w0r3.z * yy[128] + w0r3.w * yy[192];
            }
            s_h0[netA][r & 1][c][oA] = eluf(acc);
        }
        __syncthreads();

        // ---------------- Phase B: h1(p) = elu(maskB-conv(h0) + b1) ----------------
        {
            float a0 = 0.f, a1 = 0.f, a2 = 0.f, a3 = 0.f;
            #pragma unroll
            for (int t = 0; t < 5; ++t) {
                const int rr = r + DY[t], cc = c + DX[t];
                if (rr >= 0 && cc >= 0 && cc < 8) {
                    const float4* wp = reinterpret_cast<const float4*>(w1base + t * 64);
                    const float4* hp = reinterpret_cast<const float4*>(&s_h0[net][rr & 1][cc][q * 16]);
                    #pragma unroll
                    for (int j = 0; j < 4; ++j) {
                        float4 w = wp[j], h = hp[j];
                        a0 = fmaf(w.x, h.x, a0); a1 = fmaf(w.y, h.y, a1);
                        a2 = fmaf(w.z, h.z, a2); a3 = fmaf(w.w, h.w, a3);
                    }
                }
            }
            float acc = (a0 + a1) + (a2 + a3);
            acc += __shfl_xor_sync(0xffffffffu, acc, 1);
            acc += __shfl_xor_sync(0xffffffffu, acc, 2);
            if (q == 0) s_h1[net][r & 1][c][o] = eluf(acc + bias1);
        }
        __syncthreads();

        // ---------------- Phase C: h2(p) = elu(maskB-conv(h1) + b2) ----------------
        {
            float a0 = 0.f, a1 = 0.f, a2 = 0.f, a3 = 0.f;
            #pragma unroll
            for (int t = 0; t < 5; ++t) {
                const int rr = r + DY[t], cc = c + DX[t];
                if (rr >= 0 && cc >= 0 && cc < 8) {
                    const float4* wp = reinterpret_cast<const float4*>(w2base + t * 64);
                    const float4* hp = reinterpret_cast<const float4*>(&s_h1[net][rr & 1][cc][q * 16]);
                    #pragma unroll
                    for (int j = 0; j < 4; ++j) {
                        float4 w = wp[j], h = hp[j];
                        a0 = fmaf(w.x, h.x, a0); a1 = fmaf(w.y, h.y, a1);
                        a2 = fmaf(w.z, h.z, a2); a3 = fmaf(w.w, h.w, a3);
                    }
                }
            }
            float acc = (a0 + a1) + (a2 + a3);
            acc += __shfl_xor_sync(0xffffffffu, acc, 1);
            acc += __shfl_xor_sync(0xffffffffu, acc, 2);
            if (q == 0) s_h2[net][o] = eluf(acc + bias2);
        }
        __syncthreads();

        // ---------------- Phase D: 1x1 output conv (warp reductions) ----------------
        if (warp < 8) {
            float v = woA * s_h2[netD][lane] + woB * s_h2[netD][32 + lane];
            v += __shfl_xor_sync(0xffffffffu, v, 16);
            v += __shfl_xor_sync(0xffffffffu, v, 8);
            v += __shfl_xor_sync(0xffffffffu, v, 4);
            v += __shfl_xor_sync(0xffffffffu, v, 2);
            v += __shfl_xor_sync(0xffffffffu, v, 1);
            if (lane == 0) s_res[netD][cD] = v + boD;
        }
        __syncthreads();

        // ---------------- Phase E: finalize y(p), accumulate logstd ----------------
        if (tid < 4) {
            const float mu = s_res[0][tid];
            const float ls = 0.5f * s_res[1][tid];
            s_y[tid * 64 + p] = (s_x[tid * 64 + p] - mu) / (expf(ls) + EPSV);
            ls_acc += ls;
        }
        __syncthreads();
    }

    // ---- Outputs: y (B,C,H,W) flattened, then per-batch logstd sums ----
    if (tid < 256) out[b * 256 + tid] = s_y[tid];
    if (tid < 4) s_ls[tid] = ls_acc;
    __syncthreads();
    if (tid == 0) out[32 * 256 + b] = (s_ls[0] + s_ls[1]) + (s_ls[2] + s_ls[3]);
}

extern "C" void kernel_launch(void* const* d_in, const int* in_sizes, int n_in,
                              void* d_out, int out_size) {
    const float* x   = (const float*)d_in[0];
    const float* mw0 = (const float*)d_in[1];
    const float* mb0 = (const float*)d_in[2];
    const float* mw1 = (const float*)d_in[3];
    const float* mb1 = (const float*)d_in[4];
    const float* mw2 = (const float*)d_in[5];
    const float* mb2 = (const float*)d_in[6];
    const float* mwo = (const float*)d_in[7];
    const float* mbo = (const float*)d_in[8];
    const float* lw0 = (const float*)d_in[9];
    const float* lb0 = (const float*)d_in[10];
    const float* lw1 = (const float*)d_in[11];
    const float* lb1 = (const float*)d_in[12];
    const float* lw2 = (const float*)d_in[13];
    const float* lb2 = (const float*)d_in[14];
    const float* lwo = (const float*)d_in[15];
    const float* lbo = (const float*)d_in[16];
    float* out = (float*)d_out;

    pack_weights_kernel<<<328, 256>>>(mw0, mw1, mw2, lw0, lw1, lw2);
    made_ar_kernel<<<32, 512>>>(x, mb0, mb1, mb2, mwo, mbo,
                                lb0, lb1, lb2, lwo, lbo, out);
}

// round 11
// speedup vs baseline: 1.0051x; 1.0051x over previous
#include <cuda_runtime.h>
#include <math.h>

// Problem dims
#define HID 64
#define CIN 4
#define EPSV 1e-12f

// Packed weight scratch (filled by prep kernel every launch; deterministic).
// wp0: [net][o][tap*4 + i]          (mask-A taps: kidx 0..3)
// wp1: [net][o][tap][i]             (mask-B taps: kidx 0..4)
// wp2: [net][o][tap][i]
__device__ __align__(16) float g_wp0[2 * 64 * 16];
__device__ __align__(16) float g_wp1[2 * 64 * 5 * 64];
__device__ __align__(16) float g_wp2[2 * 64 * 5 * 64];

__global__ void pack_weights_kernel(
    const float* __restrict__ mw0, const float* __restrict__ mw1, const float* __restrict__ mw2,
    const float* __restrict__ lw0, const float* __restrict__ lw1, const float* __restrict__ lw2)
{
    int idx = blockIdx.x * blockDim.x + threadIdx.x;
    if (idx < 40960) {
        // g_wp1: linear = net*20480 + o*320 + tap*64 + i
        int i   = idx & 63;
        int tap = (idx >> 6) % 5;
        int o   = (idx / 320) & 63;
        int net = idx / 20480;
        const float* src = net ? lw1 : mw1;
        g_wp1[idx] = src[o * 576 + i * 9 + tap];
    } else if (idx < 81920) {
        int k   = idx - 40960;
        int i   = k & 63;
        int tap = (k >> 6) % 5;
        int o   = (k / 320) & 63;
        int net = k / 20480;
        const float* src = net ? lw2 : mw2;
        g_wp2[k] = src[o * 576 + i * 9 + tap];
    } else if (idx < 83968) {
        int k   = idx - 81920;
        int i   = k & 3;
        int tap = (k >> 2) & 3;
        int o   = (k >> 4) & 63;
        int net = k >> 10;
        const float* src = net ? lw0 : mw0;
        g_wp0[k] = src[o * 36 + i * 9 + tap];
    }
}

__device__ __forceinline__ float eluf(float v) { return v > 0.f ? v : expm1f(v); }

// One CTA per batch element. Sequential raster decode of 64 pixels.
// Phases per pixel: A: h0(p) (mask-A conv on y) -> B: h1(p) -> C: h2(p)
// -> D: 1x1 out (mu, lv_raw) -> E: y(p) = (x - mu)/(exp(0.5*lv)+eps).
__global__ __launch_bounds__(512, 1)
void made_ar_kernel(const float* __restrict__ x,
                    const float* __restrict__ mb0, const float* __restrict__ mb1,
                    const float* __restrict__ mb2, const float* __restrict__ mwo,
                    const float* __restrict__ mbo,
                    const float* __restrict__ lb0, const float* __restrict__ lb1,
                    const float* __restrict__ lb2, const float* __restrict__ lwo,
                    const float* __restrict__ lbo,
                    float* __restrict__ out)
{
    __shared__ __align__(16) float s_h0[2][2][8][64];  // [net][row ring][col][ch]
    __shared__ __align__(16) float s_h1[2][2][8][64];
    __shared__ __align__(16) float s_h2[2][64];        // post-ELU, transient per pixel
    __shared__ float s_y[4 * 64];                      // [C][H*W]
    __shared__ float s_x[4 * 64];
    __shared__ float s_res[2][4];                      // mu raw / lv raw per channel
    __shared__ float s_ls[4];

    const int tid = threadIdx.x;
    const int b   = blockIdx.x;

    if (tid < 256) s_x[tid] = x[b * 256 + tid];

    // ---- Phase-A constants (threads 0..127): net = tid>>6, o = tid&63 ----
    const int netA = tid >> 6;
    const int oA   = tid & 63;
    float4 w0r0, w0r1, w0r2, w0r3;
    float  biasA = 0.f;
    if (tid < 128) {
        const float4* wp = reinterpret_cast<const float4*>(&g_wp0[(netA * 64 + oA) * 16]);
        w0r0 = wp[0]; w0r1 = wp[1]; w0r2 = wp[2]; w0r3 = wp[3];
        biasA = (netA ? lb0 : mb0)[oA];
    }

    // ---- Phase-B/C constants: quarter-split of 320-MAC dot products ----
    const int q   = tid & 3;           // quarter of input channels
    const int o   = (tid >> 2) & 63;   // output channel
    const int net = tid >> 8;          // 0 = mu, 1 = lv (warp-uniform)
    const float bias1 = (net ? lb1 : mb1)[o];
    const float bias2 = (net ? lb2 : mb2)[o];
    const float* w1base = &g_wp1[((net * 64 + o) * 5) * 64 + q * 16];
    const float* w2base = &g_wp2[((net * 64 + o) * 5) * 64 + q * 16];

    // ---- Phase-D constants: warps 0..7 -> (net, out channel) ----
    const int warp = tid >> 5, lane = tid & 31;
    const int netD = warp >> 2, cD = warp & 3;
    float woA = 0.f, woB = 0.f, boD = 0.f;
    if (warp < 8) {
        const float* wo = netD ? lwo : mwo;
        woA = wo[cD * 64 + lane];
        woB = wo[cD * 64 + 32 + lane];
        boD = (netD ? lbo : mbo)[cD];
    }

    float ls_acc = 0.f;
    __syncthreads();

    const int DY[5] = {-1, -1, -1, 0, 0};
    const int DX[5] = {-1,  0,  1, -1, 0};

    for (int p = 0; p < 64; ++p) {
        const int r = p >> 3, c = p & 7;

        // ---------------- Phase A: h0(p) = elu(maskA-conv(y) + b0) ----------------
        if (tid < 128) {
            float acc = biasA;
            if (r > 0) {
                const int base = (r - 1) * 8 + c;
                if (c > 0) {
                    const float* yy = &s_y[base - 1];
                    acc += w0r0.x * yy[0] + w0r0.y * yy[64] + w0r0.z * yy[128] + w0r0.w * yy[192];
                }
                {
                    const float* yy = &s_y[base];
                    acc += w0r1.x * yy[0] + w0r1.y * yy[64] + w0r1.z * yy[128] + w0r1.w * yy[192];
                }
                if (c < 7) {
                    const float* yy = &s_y[base + 1];
                    acc += w0r2.x * yy[0] + w0r2.y * yy[64] + w0r2.z * yy[128] + w0r2.w * yy[192];
                }
            }
            if (c > 0) {
                const float* yy = &s_y[r * 8 + c - 1];
                acc += w0r3.x * yy[0] + w0r3.y * yy[64] + w0r3.z * yy[128] + w0r3.w * yy[192];
            }
            s_h0[netA][r & 1][c][oA] = eluf(acc);
        }
        __syncthreads();

        // ---------------- Phase B: h1(p) = elu(maskB-conv(h0) + b1) ----------------
        {
            float a0 = 0.f, a1 = 0.f, a2 = 0.f, a3 = 0.f;
            #pragma unroll
            for (int t = 0; t < 5; ++t) {
                const int rr = r + DY[t], cc = c + DX[t];
                if (rr >= 0 && cc >= 0 && cc < 8) {
                    const float4* wp = reinterpret_cast<const float4*>(w1base + t * 64);
                    const float4* hp = reinterpret_cast<const float4*>(&s_h0[net][rr & 1][cc][q * 16]);
                    #pragma unroll
                    for (int j = 0; j < 4; ++j) {
                        float4 w = wp[j], h = hp[j];
                        a0 = fmaf(w.x, h.x, a0); a1 = fmaf(w.y, h.y, a1);
                        a2 = fmaf(w.z, h.z, a2); a3 = fmaf(w.w, h.w, a3);
                    }
                }
            }
            float acc = (a0 + a1) + (a2 + a3);
            acc += __shfl_xor_sync(0xffffffffu, acc, 1);
            acc += __shfl_xor_sync(0xffffffffu, acc, 2);
            if (q == 0) s_h1[net][r & 1][c][o] = eluf(acc + bias1);
        }
        __syncthreads();

        // ---------------- Phase C: h2(p) = elu(maskB-conv(h1) + b2) ----------------
        {
            float a0 = 0.f, a1 = 0.f, a2 = 0.f, a3 = 0.f;
            #pragma unroll
            for (int t = 0; t < 5; ++t) {
                const int rr = r + DY[t], cc = c + DX[t];
                if (rr >= 0 && cc >= 0 && cc < 8) {
                    const float4* wp = reinterpret_cast<const float4*>(w2base + t * 64);
                    const float4* hp = reinterpret_cast<const float4*>(&s_h1[net][rr & 1][cc][q * 16]);
                    #pragma unroll
                    for (int j = 0; j < 4; ++j) {
                        float4 w = wp[j], h = hp[j];
                        a0 = fmaf(w.x, h.x, a0); a1 = fmaf(w.y, h.y, a1);
                        a2 = fmaf(w.z, h.z, a2); a3 = fmaf(w.w, h.w, a3);
                    }
                }
            }
            float acc = (a0 + a1) + (a2 + a3);
            acc += __shfl_xor_sync(0xffffffffu, acc, 1);
            acc += __shfl_xor_sync(0xffffffffu, acc, 2);
            if (q == 0) s_h2[net][o] = eluf(acc + bias2);
        }
        __syncthreads();

        // ---------------- Phase D: 1x1 output conv (warp reductions) ----------------
        if (warp < 8) {
            float v = woA * s_h2[netD][lane] + woB * s_h2[netD][32 + lane];
            v += __shfl_xor_sync(0xffffffffu, v, 16);
            v += __shfl_xor_sync(0xffffffffu, v, 8);
            v += __shfl_xor_sync(0xffffffffu, v, 4);
            v += __shfl_xor_sync(0xffffffffu, v, 2);
            v += __shfl_xor_sync(0xffffffffu, v, 1);
            if (lane == 0) s_res[netD][cD] = v + boD;
        }
        __syncthreads();

        // ---------------- Phase E: finalize y(p), accumulate logstd ----------------
        if (tid < 4) {
            const float mu = s_res[0][tid];
            const float ls = 0.5f * s_res[1][tid];
            s_y[tid * 64 + p] = (s_x[tid * 64 + p] - mu) / (expf(ls) + EPSV);
            ls_acc += ls;
        }
        __syncthreads();
    }

    // ---- Outputs: y (B,C,H,W) flattened, then per-batch logstd sums ----
    if (tid < 256) out[b * 256 + tid] = s_y[tid];
    if (tid < 4) s_ls[tid] = ls_acc;
    __syncthreads();
    if (tid == 0) out[32 * 256 + b] = (s_ls[0] + s_ls[1]) + (s_ls[2] + s_ls[3]);
}

extern "C" void kernel_launch(void* const* d_in, const int* in_sizes, int n_in,
                              void* d_out, int out_size) {
    const float* x   = (const float*)d_in[0];
    const float* mw0 = (const float*)d_in[1];
    const float* mb0 = (const float*)d_in[2];
    const float* mw1 = (const float*)d_in[3];
    const float* mb1 = (const float*)d_in[4];
    const float* mw2 = (const float*)d_in[5];
    const float* mb2 = (const float*)d_in[6];
    const float* mwo = (const float*)d_in[7];
    const float* mbo = (const float*)d_in[8];
    const float* lw0 = (const float*)d_in[9];
    const float* lb0 = (const float*)d_in[10];
    const float* lw1 = (const float*)d_in[11];
    const float* lb1 = (const float*)d_in[12];
    const float* lw2 = (const float*)d_in[13];
    const float* lb2 = (const float*)d_in[14];
    const float* lwo = (const float*)d_in[15];
    const float* lbo = (const float*)d_in[16];
    float* out = (float*)d_out;

    pack_weights_kernel<<<328, 256>>>(mw0, mw1, mw2, lw0, lw1, lw2);
    made_ar_kernel<<<32, 512>>>(x, mb0, mb1, mb2, mwo, mbo,
                                lb0, lb1, lb2, lwo, lbo, out);
}